// round 3
// baseline (speedup 1.0000x reference)
#include <cuda_runtime.h>
#include <cuda_bf16.h>
#include <cstddef>

// Problem constants
#define T_LEN   2048
#define BATCH   8
#define DDIM    512
#define M_ROWS  (T_LEN * BATCH)      // 16384
#define NCHUNK  16
#define CHUNK_L 128                  // T_LEN / NCHUNK
#define WARMUP  48
#define CL_SZ   8                    // CTAs per cluster

// Device-global scratch (sanctioned workaround; no runtime allocation).
__device__ float g_U[M_ROWS * DDIM];             // x@WB^T + bA + bB
__device__ float g_H[M_ROWS * DDIM];             // all h_t
__device__ float g_hbuf[NCHUNK][2][BATCH * DDIM]; // per-cluster h exchange (double buffered)

// ---------------------------------------------------------------------------
// Generic fp32 GEMM:  C[m][n] = sum_k A[m][k] * Bw[n][k]  (+ bias or addend)
// MODE 0: += b1[n] + b2[n]      MODE 1: += add[m][n] (add may alias C)
// Tiles: BM=BN=128, BK=8, 256 threads, 8x8 outputs/thread.
// ---------------------------------------------------------------------------
template <int MODE>
__global__ void __launch_bounds__(256, 2)
gemm_nt(const float* __restrict__ A, const float* __restrict__ Bw,
        const float* __restrict__ b1, const float* __restrict__ b2,
        const float* __restrict__ add, float* __restrict__ C,
        int M, int N, int K)
{
    __shared__ float As[8][128];
    __shared__ float Bs[8][128];

    const int tid   = threadIdx.x;
    const int mBase = blockIdx.x * 128;
    const int nBase = blockIdx.y * 128;

    const int lr = tid >> 1;          // 0..127 : row within tile (for loads)
    const int lq = (tid & 1) * 4;     // k offset 0 or 4
    const int tx = tid & 15;          // 0..15 : n group
    const int ty = tid >> 4;          // 0..15 : m group
    const int m0 = ty * 8;
    const int n0 = tx * 8;

    float acc[8][8];
#pragma unroll
    for (int i = 0; i < 8; ++i)
#pragma unroll
        for (int j = 0; j < 8; ++j) acc[i][j] = 0.f;

    const float* Ag = A  + (size_t)(mBase + lr) * K + lq;
    const float* Bg = Bw + (size_t)(nBase + lr) * K + lq;

    for (int kk = 0; kk < K; kk += 8) {
        float4 a4 = *(const float4*)(Ag + kk);
        float4 b4 = *(const float4*)(Bg + kk);
        __syncthreads();
        As[lq + 0][lr] = a4.x; As[lq + 1][lr] = a4.y;
        As[lq + 2][lr] = a4.z; As[lq + 3][lr] = a4.w;
        Bs[lq + 0][lr] = b4.x; Bs[lq + 1][lr] = b4.y;
        Bs[lq + 2][lr] = b4.z; Bs[lq + 3][lr] = b4.w;
        __syncthreads();
#pragma unroll
        for (int k = 0; k < 8; ++k) {
            float4 a0  = *(const float4*)&As[k][m0];
            float4 a1  = *(const float4*)&As[k][m0 + 4];
            float4 bb0 = *(const float4*)&Bs[k][n0];
            float4 bb1 = *(const float4*)&Bs[k][n0 + 4];
            float av[8] = {a0.x, a0.y, a0.z, a0.w, a1.x, a1.y, a1.z, a1.w};
            float bv[8] = {bb0.x, bb0.y, bb0.z, bb0.w, bb1.x, bb1.y, bb1.z, bb1.w};
#pragma unroll
            for (int i = 0; i < 8; ++i)
#pragma unroll
                for (int j = 0; j < 8; ++j)
                    acc[i][j] += av[i] * bv[j];
        }
    }

    float bn[8];
    if (MODE == 0) {
#pragma unroll
        for (int j = 0; j < 8; ++j)
            bn[j] = b1[nBase + n0 + j] + b2[nBase + n0 + j];
    }
#pragma unroll
    for (int i = 0; i < 8; ++i) {
        const int gm = mBase + m0 + i;
        const size_t rowBase = (size_t)gm * N + nBase + n0;
#pragma unroll
        for (int j = 0; j < 8; ++j) {
            float v = acc[i][j];
            if (MODE == 0) v += bn[j];
            else           v += add[rowBase + j];
            C[rowBase + j] = v;
        }
    }
}

// ---------------------------------------------------------------------------
// Chunked scan:  h_t = h_{t-1} @ WA^T + U_t
// Grid: 128 CTAs = 16 clusters x 8 CTAs. Each cluster owns one time-chunk of
// L=128 steps (chunks >0 warm up W=48 steps from h=0; chunk 0 starts at h0).
// CTA r holds WA rows [r*64, r*64+64) in SMEM (swizzled). Per step each CTA
// computes its [8 x 64] slice of h_new, slices are merged through a
// double-buffered global buffer with one barrier.cluster per step.
// ---------------------------------------------------------------------------
__global__ void __cluster_dims__(CL_SZ, 1, 1) __launch_bounds__(256, 1)
ssm_scan(const float* __restrict__ WA, const float* __restrict__ h0)
{
    extern __shared__ float smem[];
    float4* WAs  = (float4*)smem;            // 64*128 float4 (swizzled) = 128 KB
    float*  h_s  = smem + 4 * 8192;          // 8*512 floats = 16 KB
    float*  red  = h_s + 4096;               // 8*512 floats = 16 KB
    float4* h_s4 = (float4*)h_s;

    const int tid = threadIdx.x;
    const int bid = blockIdx.x;
    const int r   = bid & (CL_SZ - 1);       // rank in cluster
    const int cid = bid / CL_SZ;             // chunk id

    // Load WA slice, swizzled: f4 slot = j*128 + (kv ^ (j & 7))
    const float4* WAg4 = (const float4*)WA;
    for (int idx = tid; idx < 64 * 128; idx += 256) {
        const int j  = idx >> 7;
        const int kv = idx & 127;
        WAs[j * 128 + (kv ^ (j & 7))] = WAg4[(r * 64 + j) * 128 + kv];
    }
    // Init h state
    if (cid == 0) {
        const float4* h0g = (const float4*)h0;
        for (int i = tid; i < 1024; i += 256) h_s4[i] = h0g[i];
    } else {
        for (int i = tid; i < 1024; i += 256) h_s4[i] = make_float4(0.f, 0.f, 0.f, 0.f);
    }
    __syncthreads();

    const int tOut   = cid * CHUNK_L;
    const int tBegin = (cid == 0) ? 0 : tOut - WARMUP;
    const int tEnd   = tOut + CHUNK_L;

    const int jg  = tid & 31;        // lanes -> 32 consecutive j (broadcast-friendly)
    const int ks  = tid >> 5;        // 8-way k split
    const int j0  = jg;
    const int j1  = jg + 32;         // j0 & 7 == j1 & 7: same swizzle phase
    const int kv0 = ks << 4;         // 16 float4 per thread per step
    const int sw0 = j0 * 128;
    const int sw1 = j1 * 128;
    const int swx = jg & 7;

    for (int t = tBegin; t < tEnd; ++t) {
        float acc0[8], acc1[8];
#pragma unroll
        for (int b = 0; b < 8; ++b) { acc0[b] = 0.f; acc1[b] = 0.f; }

#pragma unroll
        for (int kk = 0; kk < 16; ++kk) {
            const int kv = kv0 + kk;
            const float4 wa0 = WAs[sw0 + (kv ^ swx)];
            const float4 wa1 = WAs[sw1 + (kv ^ swx)];
#pragma unroll
            for (int b = 0; b < 8; ++b) {
                const float4 h4 = h_s4[b * 128 + kv];
                acc0[b] += h4.x * wa0.x + h4.y * wa0.y + h4.z * wa0.z + h4.w * wa0.w;
                acc1[b] += h4.x * wa1.x + h4.y * wa1.y + h4.z * wa1.z + h4.w * wa1.w;
            }
        }

        // k-split partials -> SMEM
#pragma unroll
        for (int b = 0; b < 8; ++b) {
            red[ks * 512 + b * 64 + j0] = acc0[b];
            red[ks * 512 + b * 64 + j1] = acc1[b];
        }
        __syncthreads();

        float* hb = g_hbuf[cid][t & 1];
#pragma unroll
        for (int rr = 0; rr < 2; ++rr) {
            const int o = tid + rr * 256;      // 0..511 over (b, j)
            const int b = o >> 6;
            const int j = o & 63;
            float s = red[o] + red[512 + o] + red[1024 + o] + red[1536 + o]
                    + red[2048 + o] + red[2560 + o] + red[3072 + o] + red[3584 + o];
            const int jglob = r * 64 + j;
            const float v = s + __ldg(&g_U[(t * BATCH + b) * DDIM + jglob]);
            __stcg(&hb[b * DDIM + jglob], v);                 // L2-only, cluster-visible
            if (t >= tOut) g_H[(t * BATCH + b) * DDIM + jglob] = v;
        }

        // Cluster barrier: arrive=release, wait=acquire (also invalidates L1D)
        asm volatile("barrier.cluster.arrive.aligned;\n" ::: "memory");
        asm volatile("barrier.cluster.wait.aligned;\n" ::: "memory");

        // Reload the full merged h for the next step
        const float4* hb4 = (const float4*)hb;
        for (int i = tid; i < 1024; i += 256) h_s4[i] = __ldcg(hb4 + i);
        __syncthreads();
    }
}

// ---------------------------------------------------------------------------
extern "C" void kernel_launch(void* const* d_in, const int* in_sizes, int n_in,
                              void* d_out, int out_size)
{
    (void)in_sizes; (void)n_in; (void)out_size;
    const float* X  = (const float*)d_in[0];  // sequence [T,B,D]
    const float* h0 = (const float*)d_in[1];
    const float* WA = (const float*)d_in[2];
    const float* bA = (const float*)d_in[3];
    const float* WB = (const float*)d_in[4];
    const float* bB = (const float*)d_in[5];
    const float* WC = (const float*)d_in[6];
    const float* bC = (const float*)d_in[7];
    const float* WD = (const float*)d_in[8];
    const float* bD = (const float*)d_in[9];
    float* Y = (float*)d_out;

    float* U = nullptr; float* H = nullptr;
    cudaGetSymbolAddress((void**)&U, g_U);
    cudaGetSymbolAddress((void**)&H, g_H);

    cudaFuncSetAttribute(ssm_scan, cudaFuncAttributeMaxDynamicSharedMemorySize,
                         (64 * 128) * 16 + 4096 * 4 + 4096 * 4);   // 160 KB

    const dim3 gGrid(M_ROWS / 128, DDIM / 128);   // (128, 4)

    // 1) U = X @ WB^T + bA + bB   (bA folded in: added every recurrence step)
    gemm_nt<0><<<gGrid, 256>>>(X, WB, bA, bB, nullptr, U, M_ROWS, DDIM, DDIM);
    // 2) V = X @ WD^T + bC + bD   -> stored directly into Y (d_out)
    gemm_nt<0><<<gGrid, 256>>>(X, WD, bC, bD, nullptr, Y, M_ROWS, DDIM, DDIM);
    // 3) Chunked scan -> g_H
    ssm_scan<<<NCHUNK * CL_SZ, 256, (64 * 128) * 16 + 4096 * 4 + 4096 * 4>>>(WA, h0);
    // 4) Y = H @ WC^T + V (in place: same-element read-then-write per thread)
    gemm_nt<1><<<gGrid, 256>>>(H, WC, nullptr, nullptr, Y, Y, M_ROWS, DDIM, DDIM);
}

// round 4
// speedup vs baseline: 1.0538x; 1.0538x over previous
#include <cuda_runtime.h>
#include <cuda_bf16.h>
#include <cstddef>

// Problem constants
#define T_LEN   2048
#define BATCH   8
#define DDIM    512
#define M_ROWS  (T_LEN * BATCH)      // 16384
#define NCHUNK  16
#define CHUNK_L 128                  // T_LEN / NCHUNK
#define WARMUP  32
#define CL_SZ   8                    // CTAs per cluster

typedef unsigned long long u64;

// Packed fp32x2 FMA (Blackwell FFMA2): d.lo += a.lo*b.lo, d.hi += a.hi*b.hi
#define FMA2(d, a, b) \
    asm("fma.rn.f32x2 %0, %1, %2, %0;" : "+l"(d) : "l"(a), "l"(b))

union F4U2 { float4 f4; struct { u64 lo, hi; } u; };

// Device-global scratch (sanctioned workaround; no runtime allocation).
__device__ float g_U[M_ROWS * DDIM];             // x@WB^T + bA + bB
__device__ float g_H[M_ROWS * DDIM];             // all h_t
__device__ float g_hbuf[NCHUNK][2][BATCH * DDIM]; // per-cluster h exchange (double buffered)

// ---------------------------------------------------------------------------
// fp32 GEMM with FFMA2 inner loop + global->reg software pipeline.
// C[m][n] = sum_k A[m][k] * Bw[n][k]  (+ bias or addend)
// MODE 0: += b1[n] + b2[n]      MODE 1: += add[m][n] (add may alias C)
// Tiles: BM=BN=128, BK=8, 256 threads, 8x8 outputs/thread (as 8x4 f32x2).
// ---------------------------------------------------------------------------
template <int MODE>
__global__ void __launch_bounds__(256, 2)
gemm_nt(const float* __restrict__ A, const float* __restrict__ Bw,
        const float* __restrict__ b1, const float* __restrict__ b2,
        const float* __restrict__ add, float* __restrict__ C,
        int M, int N, int K)
{
    __shared__ float As[8][128];
    __shared__ float Bs[8][128];

    const int tid   = threadIdx.x;
    const int mBase = blockIdx.x * 128;
    const int nBase = blockIdx.y * 128;

    const int lr = tid >> 1;          // 0..127 : row within tile (for loads)
    const int lq = (tid & 1) * 4;     // k offset 0 or 4
    const int tx = tid & 15;          // 0..15 : n group
    const int ty = tid >> 4;          // 0..15 : m group
    const int m0 = ty * 8;
    const int n0 = tx * 8;

    u64 acc2[8][4];
#pragma unroll
    for (int i = 0; i < 8; ++i)
#pragma unroll
        for (int j = 0; j < 4; ++j) acc2[i][j] = 0ull;

    const float* Ag = A  + (size_t)(mBase + lr) * K + lq;
    const float* Bg = Bw + (size_t)(nBase + lr) * K + lq;

    // Software pipeline: regs hold the tile for iteration kk while kk-1 computes.
    float4 a4 = *(const float4*)(Ag);
    float4 b4 = *(const float4*)(Bg);

    for (int kk = 0; kk < K; kk += 8) {
        __syncthreads();
        As[lq + 0][lr] = a4.x; As[lq + 1][lr] = a4.y;
        As[lq + 2][lr] = a4.z; As[lq + 3][lr] = a4.w;
        Bs[lq + 0][lr] = b4.x; Bs[lq + 1][lr] = b4.y;
        Bs[lq + 2][lr] = b4.z; Bs[lq + 3][lr] = b4.w;
        __syncthreads();
        if (kk + 8 < K) {               // prefetch next tile under this compute
            a4 = *(const float4*)(Ag + kk + 8);
            b4 = *(const float4*)(Bg + kk + 8);
        }
#pragma unroll
        for (int k = 0; k < 8; ++k) {
            float4 a0 = *(const float4*)&As[k][m0];
            float4 a1 = *(const float4*)&As[k][m0 + 4];
            F4U2 bb0, bb1;
            bb0.f4 = *(const float4*)&Bs[k][n0];
            bb1.f4 = *(const float4*)&Bs[k][n0 + 4];
            float av[8] = {a0.x, a0.y, a0.z, a0.w, a1.x, a1.y, a1.z, a1.w};
            u64 bp[4] = {bb0.u.lo, bb0.u.hi, bb1.u.lo, bb1.u.hi};
#pragma unroll
            for (int i = 0; i < 8; ++i) {
                u64 ap;
                asm("mov.b64 %0, {%1, %2};" : "=l"(ap) : "f"(av[i]), "f"(av[i]));
                FMA2(acc2[i][0], ap, bp[0]);
                FMA2(acc2[i][1], ap, bp[1]);
                FMA2(acc2[i][2], ap, bp[2]);
                FMA2(acc2[i][3], ap, bp[3]);
            }
        }
    }

    float bn[8];
    if (MODE == 0) {
#pragma unroll
        for (int j = 0; j < 8; ++j)
            bn[j] = b1[nBase + n0 + j] + b2[nBase + n0 + j];
    }
#pragma unroll
    for (int i = 0; i < 8; ++i) {
        const int gm = mBase + m0 + i;
        const size_t rowBase = (size_t)gm * N + nBase + n0;
        float acc[8];
#pragma unroll
        for (int jp = 0; jp < 4; ++jp) {
            float lo, hi;
            asm("mov.b64 {%0, %1}, %2;" : "=f"(lo), "=f"(hi) : "l"(acc2[i][jp]));
            acc[2 * jp] = lo; acc[2 * jp + 1] = hi;
        }
#pragma unroll
        for (int j = 0; j < 8; ++j) {
            float v = acc[j];
            if (MODE == 0) v += bn[j];
            else           v += add[rowBase + j];
            C[rowBase + j] = v;
        }
    }
}

// ---------------------------------------------------------------------------
// Chunked scan:  h_t = h_{t-1} @ WA^T + U_t
// Grid: 128 CTAs = 16 clusters x 8 CTAs. Each cluster owns one time-chunk of
// L=128 steps (chunks >0 warm up W=32 steps from h=0; chunk 0 starts at h0).
// CTA r holds WA rows [r*64, r*64+64) in SMEM (swizzled). Per step each CTA
// computes its [8 x 64] slice of h_new with FFMA2 dot products; slices are
// merged through a double-buffered L2 buffer with one barrier.cluster/step.
// ---------------------------------------------------------------------------
__global__ void __cluster_dims__(CL_SZ, 1, 1) __launch_bounds__(256, 1)
ssm_scan(const float* __restrict__ WA, const float* __restrict__ h0)
{
    extern __shared__ float smem[];
    float4* WAs  = (float4*)smem;            // 64*128 float4 (swizzled) = 128 KB
    float*  h_s  = smem + 4 * 8192;          // 8*512 floats = 16 KB
    float*  red  = h_s + 4096;               // 8*512 floats = 16 KB
    float4* h_s4 = (float4*)h_s;

    const int tid = threadIdx.x;
    const int bid = blockIdx.x;
    const int r   = bid & (CL_SZ - 1);       // rank in cluster
    const int cid = bid / CL_SZ;             // chunk id

    // Load WA slice, swizzled: f4 slot = j*128 + (kv ^ (j & 7))
    const float4* WAg4 = (const float4*)WA;
    for (int idx = tid; idx < 64 * 128; idx += 256) {
        const int j  = idx >> 7;
        const int kv = idx & 127;
        WAs[j * 128 + (kv ^ (j & 7))] = WAg4[(r * 64 + j) * 128 + kv];
    }
    // Init h state
    if (cid == 0) {
        const float4* h0g = (const float4*)h0;
        for (int i = tid; i < 1024; i += 256) h_s4[i] = h0g[i];
    } else {
        for (int i = tid; i < 1024; i += 256) h_s4[i] = make_float4(0.f, 0.f, 0.f, 0.f);
    }
    __syncthreads();

    const int tOut   = cid * CHUNK_L;
    const int tBegin = (cid == 0) ? 0 : tOut - WARMUP;
    const int tEnd   = tOut + CHUNK_L;

    const int jg  = tid & 31;        // lanes -> 32 consecutive j (broadcast-friendly)
    const int ks  = tid >> 5;        // 8-way k split
    const int j0  = jg;
    const int j1  = jg + 32;         // j0 & 7 == j1 & 7: same swizzle phase
    const int kv0 = ks << 4;         // 16 float4 per thread per step
    const int sw0 = j0 * 128;
    const int sw1 = j1 * 128;
    const int swx = jg & 7;

    // Per-thread output coordinates for the merge stage (2 outputs/thread)
    const int ob0 = tid >> 6,          oj0 = tid & 63;
    const int ob1 = (tid + 256) >> 6,  oj1 = (tid + 256) & 63;
    const int og0 = r * 64 + oj0,      og1 = r * 64 + oj1;

    for (int t = tBegin; t < tEnd; ++t) {
        // Prefetch this step's input-drive values early (DRAM latency cover)
        const float u0 = __ldg(&g_U[(t * BATCH + ob0) * DDIM + og0]);
        const float u1 = __ldg(&g_U[(t * BATCH + ob1) * DDIM + og1]);

        u64 acc2_0[8], acc2_1[8];
#pragma unroll
        for (int b = 0; b < 8; ++b) { acc2_0[b] = 0ull; acc2_1[b] = 0ull; }

#pragma unroll
        for (int kk = 0; kk < 16; ++kk) {
            const int kv = kv0 + kk;
            F4U2 wa0, wa1;
            wa0.f4 = WAs[sw0 + (kv ^ swx)];
            wa1.f4 = WAs[sw1 + (kv ^ swx)];
#pragma unroll
            for (int b = 0; b < 8; ++b) {
                F4U2 h4; h4.f4 = h_s4[b * 128 + kv];
                FMA2(acc2_0[b], h4.u.lo, wa0.u.lo);
                FMA2(acc2_0[b], h4.u.hi, wa0.u.hi);
                FMA2(acc2_1[b], h4.u.lo, wa1.u.lo);
                FMA2(acc2_1[b], h4.u.hi, wa1.u.hi);
            }
        }

        // Horizontal add + k-split partials -> SMEM
#pragma unroll
        for (int b = 0; b < 8; ++b) {
            float lo, hi, s0, s1;
            asm("mov.b64 {%0, %1}, %2;" : "=f"(lo), "=f"(hi) : "l"(acc2_0[b]));
            s0 = lo + hi;
            asm("mov.b64 {%0, %1}, %2;" : "=f"(lo), "=f"(hi) : "l"(acc2_1[b]));
            s1 = lo + hi;
            red[ks * 512 + b * 64 + j0] = s0;
            red[ks * 512 + b * 64 + j1] = s1;
        }
        __syncthreads();

        float* hb = g_hbuf[cid][t & 1];
        {
            const int o = tid;
            float s = red[o] + red[512 + o] + red[1024 + o] + red[1536 + o]
                    + red[2048 + o] + red[2560 + o] + red[3072 + o] + red[3584 + o];
            const float v = s + u0;
            __stcg(&hb[ob0 * DDIM + og0], v);
            if (t >= tOut) g_H[(t * BATCH + ob0) * DDIM + og0] = v;
        }
        {
            const int o = tid + 256;
            float s = red[o] + red[512 + o] + red[1024 + o] + red[1536 + o]
                    + red[2048 + o] + red[2560 + o] + red[3072 + o] + red[3584 + o];
            const float v = s + u1;
            __stcg(&hb[ob1 * DDIM + og1], v);
            if (t >= tOut) g_H[(t * BATCH + ob1) * DDIM + og1] = v;
        }

        // Cluster barrier: arrive=release, wait=acquire (also invalidates L1D)
        asm volatile("barrier.cluster.arrive.aligned;\n" ::: "memory");
        asm volatile("barrier.cluster.wait.aligned;\n" ::: "memory");

        // Reload the full merged h for the next step
        const float4* hb4 = (const float4*)hb;
        for (int i = tid; i < 1024; i += 256) h_s4[i] = __ldcg(hb4 + i);
        __syncthreads();
    }
}

// ---------------------------------------------------------------------------
extern "C" void kernel_launch(void* const* d_in, const int* in_sizes, int n_in,
                              void* d_out, int out_size)
{
    (void)in_sizes; (void)n_in; (void)out_size;
    const float* X  = (const float*)d_in[0];  // sequence [T,B,D]
    const float* h0 = (const float*)d_in[1];
    const float* WA = (const float*)d_in[2];
    const float* bA = (const float*)d_in[3];
    const float* WB = (const float*)d_in[4];
    const float* bB = (const float*)d_in[5];
    const float* WC = (const float*)d_in[6];
    const float* bC = (const float*)d_in[7];
    const float* WD = (const float*)d_in[8];
    const float* bD = (const float*)d_in[9];
    float* Y = (float*)d_out;

    float* U = nullptr; float* H = nullptr;
    cudaGetSymbolAddress((void**)&U, g_U);
    cudaGetSymbolAddress((void**)&H, g_H);

    cudaFuncSetAttribute(ssm_scan, cudaFuncAttributeMaxDynamicSharedMemorySize,
                         (64 * 128) * 16 + 4096 * 4 + 4096 * 4);   // 160 KB

    const dim3 gGrid(M_ROWS / 128, DDIM / 128);   // (128, 4)

    // 1) U = X @ WB^T + bA + bB   (bA folded in: added every recurrence step)
    gemm_nt<0><<<gGrid, 256>>>(X, WB, bA, bB, nullptr, U, M_ROWS, DDIM, DDIM);
    // 2) V = X @ WD^T + bC + bD   -> stored directly into Y (d_out)
    gemm_nt<0><<<gGrid, 256>>>(X, WD, bC, bD, nullptr, Y, M_ROWS, DDIM, DDIM);
    // 3) Chunked scan -> g_H
    ssm_scan<<<NCHUNK * CL_SZ, 256, (64 * 128) * 16 + 4096 * 4 + 4096 * 4>>>(WA, h0);
    // 4) Y = H @ WC^T + V (in place: same-element read-then-write per thread)
    gemm_nt<1><<<gGrid, 256>>>(H, WC, nullptr, nullptr, Y, Y, M_ROWS, DDIM, DDIM);
}

// round 16
// speedup vs baseline: 1.5536x; 1.4742x over previous
#include <cuda_runtime.h>
#include <cuda_bf16.h>
#include <cstdint>
#include <cstddef>

// Problem constants
#define T_LEN   2048
#define BATCH   8
#define DDIM    512
#define M_ROWS  (T_LEN * BATCH)      // 16384
#define NCHUNK  16
#define CHUNK_L 128                  // T_LEN / NCHUNK
#define WARMUP  24
#define CL_SZ   8                    // CTAs per cluster

typedef unsigned long long u64;

// Packed fp32x2 FMA (Blackwell FFMA2)
#define FMA2(d, a, b) \
    asm("fma.rn.f32x2 %0, %1, %2, %0;" : "+l"(d) : "l"(a), "l"(b))

union F4U2 { float4 f4; struct { u64 lo, hi; } u; };

// Device-global scratch (sanctioned workaround; no runtime allocation).
__device__ float g_U[M_ROWS * DDIM];             // x@WB^T + bA + bB
__device__ float g_H[M_ROWS * DDIM];             // all h_t
__device__ float g_hbuf[NCHUNK][2][BATCH * DDIM]; // per-cluster h exchange (double buffered)

// Single dynamic-SMEM extern for the TU (used only by ssm_scan).
extern __shared__ char dynsmem[];

// Warp-level bf16 MMA (sm_80+ PTX; works on plain sm_103 target — tcgen05 does NOT).
#define MMA16816(c, a0, a1, a2, a3, b0, b1) \
    asm volatile("mma.sync.aligned.m16n8k16.row.col.f32.bf16.bf16.f32 " \
        "{%0,%1,%2,%3}, {%4,%5,%6,%7}, {%8,%9}, {%0,%1,%2,%3};" \
        : "+f"((c)[0]), "+f"((c)[1]), "+f"((c)[2]), "+f"((c)[3]) \
        : "r"(a0), "r"(a1), "r"(a2), "r"(a3), "r"(b0), "r"(b1))

// Split fp32 pair -> packed bf16x2 hi word and lo (residual) word. Low 16 bits
// hold the FIRST (lower-k) element, matching mma.sync's packed-pair order.
__device__ __forceinline__ void split2(float a, float b, uint32_t& whi, uint32_t& wlo) {
    __nv_bfloat16 h0 = __float2bfloat16(a), h1 = __float2bfloat16(b);
    __nv_bfloat16 l0 = __float2bfloat16(a - __bfloat162float(h0));
    __nv_bfloat16 l1 = __float2bfloat16(b - __bfloat162float(h1));
    __nv_bfloat162 H; H.x = h0; H.y = h1;
    __nv_bfloat162 L; L.x = l0; L.y = l1;
    whi = *reinterpret_cast<uint32_t*>(&H);
    wlo = *reinterpret_cast<uint32_t*>(&L);
}

// ===========================================================================
// Tensor-core GEMM via mma.sync: C[m][n] = sum_k A[m][k]*Bw[n][k] (+bias/+add)
// CTA tile 128x64, 8 warps (4x2), warp tile 32x32, K in 16 chunks of 32.
// fp32 -> bf16 hi+lo planes in SMEM (3 passes: hh + hl + lh, fp32 acc).
// SMEM rows padded to 40 bf16 (80B): frag loads (row*20+tg u32) conflict-free.
// MODE 0: +b1[n]+b2[n].  MODE 1: +add[m][n] (add may alias C).
// ===========================================================================
#define APITCH 20   // u32 pitch (40 bf16 = 80 B)
template <int MODE>
__global__ void __launch_bounds__(256, 2)
mma_gemm(const float* __restrict__ A, const float* __restrict__ Bw,
         const float* __restrict__ b1, const float* __restrict__ b2,
         const float* __restrict__ add, float* __restrict__ C)
{
    __shared__ __align__(16) uint32_t Ah32[128 * APITCH];
    __shared__ __align__(16) uint32_t Al32[128 * APITCH];
    __shared__ __align__(16) uint32_t Bh32[64 * APITCH];
    __shared__ __align__(16) uint32_t Bl32[64 * APITCH];

    const int tid  = threadIdx.x;
    const int wid  = tid >> 5, lane = tid & 31;
    const int g    = lane >> 2, tg = lane & 3;
    const int wm   = wid >> 1,  wn = wid & 1;
    const int mBase = blockIdx.x * 128, nBase = blockIdx.y * 64;

    float acc[2][4][4];
#pragma unroll
    for (int m = 0; m < 2; ++m)
#pragma unroll
        for (int nf = 0; nf < 4; ++nf)
#pragma unroll
            for (int q = 0; q < 4; ++q) acc[m][nf][q] = 0.f;

    // Per-thread global-load map for one 32-wide K chunk:
    // A: 128x32 f32 = 1024 float4 -> 4/thread; B: 64x32 = 512 float4 -> 2/thread.
    const int arow[4] = { (tid + 0)   >> 3, (tid + 256) >> 3,
                          (tid + 512) >> 3, (tid + 768) >> 3 };
    const int ac4 [4] = { (tid + 0) & 7, (tid + 256) & 7,
                          (tid + 512) & 7, (tid + 768) & 7 };
    const int brow[2] = { (tid + 0) >> 3, (tid + 256) >> 3 };
    const int bc4 [2] = { (tid + 0) & 7, (tid + 256) & 7 };

    float4 pA[4], pB[2];
#pragma unroll
    for (int i = 0; i < 4; ++i)
        pA[i] = *(const float4*)(A + (size_t)(mBase + arow[i]) * 512 + ac4[i] * 4);
#pragma unroll
    for (int i = 0; i < 2; ++i)
        pB[i] = *(const float4*)(Bw + (size_t)(nBase + brow[i]) * 512 + bc4[i] * 4);

    for (int ch = 0; ch < 16; ++ch) {
        __syncthreads();                      // SMEM free (prev chunk consumed)
        // Split & store chunk to SMEM planes
#pragma unroll
        for (int i = 0; i < 4; ++i) {
            uint32_t h0, l0, h1, l1;
            split2(pA[i].x, pA[i].y, h0, l0);
            split2(pA[i].z, pA[i].w, h1, l1);
            const int o = arow[i] * APITCH + ac4[i] * 2;
            Ah32[o] = h0; Ah32[o + 1] = h1;
            Al32[o] = l0; Al32[o + 1] = l1;
        }
#pragma unroll
        for (int i = 0; i < 2; ++i) {
            uint32_t h0, l0, h1, l1;
            split2(pB[i].x, pB[i].y, h0, l0);
            split2(pB[i].z, pB[i].w, h1, l1);
            const int o = brow[i] * APITCH + bc4[i] * 2;
            Bh32[o] = h0; Bh32[o + 1] = h1;
            Bl32[o] = l0; Bl32[o + 1] = l1;
        }
        __syncthreads();

        if (ch < 15) {                        // prefetch next chunk under the mma work
            const int k0 = (ch + 1) * 32;
#pragma unroll
            for (int i = 0; i < 4; ++i)
                pA[i] = *(const float4*)(A + (size_t)(mBase + arow[i]) * 512 + k0 + ac4[i] * 4);
#pragma unroll
            for (int i = 0; i < 2; ++i)
                pB[i] = *(const float4*)(Bw + (size_t)(nBase + brow[i]) * 512 + k0 + bc4[i] * 4);
        }

        // Compute: 2 k16 steps per chunk
#pragma unroll
        for (int kb2 = 0; kb2 < 16; kb2 += 8) {   // u32 k-base: 0 (k=0..15), 8 (k=16..31)
            uint32_t ah[2][4], al[2][4];
#pragma unroll
            for (int m = 0; m < 2; ++m) {
                const int r0 = (wm * 32 + m * 16 + g) * APITCH + kb2 + tg;
                const int r8 = r0 + 8 * APITCH;
                ah[m][0] = Ah32[r0];     ah[m][1] = Ah32[r8];
                ah[m][2] = Ah32[r0 + 4]; ah[m][3] = Ah32[r8 + 4];
                al[m][0] = Al32[r0];     al[m][1] = Al32[r8];
                al[m][2] = Al32[r0 + 4]; al[m][3] = Al32[r8 + 4];
            }
#pragma unroll
            for (int nf = 0; nf < 4; ++nf) {
                const int rb = (wn * 32 + nf * 8 + g) * APITCH + kb2 + tg;
                const uint32_t bh0 = Bh32[rb], bh1 = Bh32[rb + 4];
                const uint32_t bl0 = Bl32[rb], bl1 = Bl32[rb + 4];
#pragma unroll
                for (int m = 0; m < 2; ++m) {
                    MMA16816(acc[m][nf], ah[m][0], ah[m][1], ah[m][2], ah[m][3], bh0, bh1);
                    MMA16816(acc[m][nf], ah[m][0], ah[m][1], ah[m][2], ah[m][3], bl0, bl1);
                    MMA16816(acc[m][nf], al[m][0], al[m][1], al[m][2], al[m][3], bh0, bh1);
                }
            }
        }
    }

    // Epilogue: c0,c1 -> (row, col..col+1), c2,c3 -> (row+8, same cols)
#pragma unroll
    for (int m = 0; m < 2; ++m) {
#pragma unroll
        for (int nf = 0; nf < 4; ++nf) {
            const int row = mBase + wm * 32 + m * 16 + g;
            const int col = nBase + wn * 32 + nf * 8 + tg * 2;
            float2 v0 = make_float2(acc[m][nf][0], acc[m][nf][1]);
            float2 v1 = make_float2(acc[m][nf][2], acc[m][nf][3]);
            if (MODE == 0) {
                const float bb0 = b1[col] + b2[col];
                const float bb1 = b1[col + 1] + b2[col + 1];
                v0.x += bb0; v0.y += bb1;
                v1.x += bb0; v1.y += bb1;
            } else {
                const float2 a0 = *(const float2*)(add + (size_t)row * 512 + col);
                const float2 a1 = *(const float2*)(add + (size_t)(row + 8) * 512 + col);
                v0.x += a0.x; v0.y += a0.y;
                v1.x += a1.x; v1.y += a1.y;
            }
            *(float2*)(C + (size_t)row * 512 + col) = v0;
            *(float2*)(C + (size_t)(row + 8) * 512 + col) = v1;
        }
    }
}

// ---------------------------------------------------------------------------
// Chunked scan:  h_t = h_{t-1} @ WA^T + U_t   (R5 version, unchanged)
// ---------------------------------------------------------------------------
__global__ void __cluster_dims__(CL_SZ, 1, 1) __launch_bounds__(256, 1)
ssm_scan(const float* __restrict__ WA, const float* __restrict__ h0)
{
    float* smem = (float*)dynsmem;
    float4* WAs  = (float4*)smem;            // 64*128 float4 (swizzled) = 128 KB
    float*  h_s  = smem + 4 * 8192;          // 8*512 floats = 16 KB
    float*  red  = h_s + 4096;               // 8*512 floats = 16 KB
    float4* h_s4 = (float4*)h_s;

    const int tid = threadIdx.x;
    const int bid = blockIdx.x;
    const int r   = bid & (CL_SZ - 1);
    const int cid = bid / CL_SZ;

    const float4* WAg4 = (const float4*)WA;
    for (int idx = tid; idx < 64 * 128; idx += 256) {
        const int j  = idx >> 7;
        const int kv = idx & 127;
        WAs[j * 128 + (kv ^ (j & 7))] = WAg4[(r * 64 + j) * 128 + kv];
    }
    if (cid == 0) {
        const float4* h0g = (const float4*)h0;
        for (int i = tid; i < 1024; i += 256) h_s4[i] = h0g[i];
    } else {
        for (int i = tid; i < 1024; i += 256) h_s4[i] = make_float4(0.f, 0.f, 0.f, 0.f);
    }
    __syncthreads();

    const int tOut   = cid * CHUNK_L;
    const int tBegin = (cid == 0) ? 0 : tOut - WARMUP;
    const int tEnd   = tOut + CHUNK_L;

    const int jg  = tid & 31;
    const int ks  = tid >> 5;
    const int j0  = jg;
    const int j1  = jg + 32;
    const int kv0 = ks << 4;
    const int sw0 = j0 * 128;
    const int sw1 = j1 * 128;
    const int swx = jg & 7;

    const int st_b  = jg >> 2;
    const int st_kv = kv0 + (jg & 3) * 4;
    const int st_idx = st_b * 128 + st_kv;

    const int ob0 = tid >> 6,          oj0 = tid & 63;
    const int ob1 = (tid + 256) >> 6,  oj1 = (tid + 256) & 63;
    const int og0 = r * 64 + oj0,      og1 = r * 64 + oj1;

    float u0 = __ldg(&g_U[(tBegin * BATCH + ob0) * DDIM + og0]);
    float u1 = __ldg(&g_U[(tBegin * BATCH + ob1) * DDIM + og1]);

    for (int t = tBegin; t < tEnd; ++t) {
        if (t != tBegin) {
            const float4* pb4 = (const float4*)g_hbuf[cid][(t - 1) & 1];
#pragma unroll
            for (int j = 0; j < 4; ++j)
                h_s4[st_idx + j] = __ldcg(pb4 + st_idx + j);
            __syncwarp();
        }

        u64 acc2_0[8], acc2_1[8];
#pragma unroll
        for (int b = 0; b < 8; ++b) { acc2_0[b] = 0ull; acc2_1[b] = 0ull; }

#pragma unroll
        for (int kk = 0; kk < 16; ++kk) {
            const int kv = kv0 + kk;
            F4U2 wa0, wa1;
            wa0.f4 = WAs[sw0 + (kv ^ swx)];
            wa1.f4 = WAs[sw1 + (kv ^ swx)];
#pragma unroll
            for (int b = 0; b < 8; ++b) {
                F4U2 h4; h4.f4 = h_s4[b * 128 + kv];
                FMA2(acc2_0[b], h4.u.lo, wa0.u.lo);
                FMA2(acc2_0[b], h4.u.hi, wa0.u.hi);
                FMA2(acc2_1[b], h4.u.lo, wa1.u.lo);
                FMA2(acc2_1[b], h4.u.hi, wa1.u.hi);
            }
        }

#pragma unroll
        for (int b = 0; b < 8; ++b) {
            float lo, hi, s0, s1;
            asm("mov.b64 {%0, %1}, %2;" : "=f"(lo), "=f"(hi) : "l"(acc2_0[b]));
            s0 = lo + hi;
            asm("mov.b64 {%0, %1}, %2;" : "=f"(lo), "=f"(hi) : "l"(acc2_1[b]));
            s1 = lo + hi;
            red[ks * 512 + b * 64 + j0] = s0;
            red[ks * 512 + b * 64 + j1] = s1;
        }
        __syncthreads();

        float* hb = g_hbuf[cid][t & 1];
        float v0, v1;
        {
            const int o = tid;
            float s = red[o] + red[512 + o] + red[1024 + o] + red[1536 + o]
                    + red[2048 + o] + red[2560 + o] + red[3072 + o] + red[3584 + o];
            v0 = s + u0;
            __stcg(&hb[ob0 * DDIM + og0], v0);
        }
        {
            const int o = tid + 256;
            float s = red[o] + red[512 + o] + red[1024 + o] + red[1536 + o]
                    + red[2048 + o] + red[2560 + o] + red[3072 + o] + red[3584 + o];
            v1 = s + u1;
            __stcg(&hb[ob1 * DDIM + og1], v1);
        }

        asm volatile("barrier.cluster.arrive.aligned;\n" ::: "memory");

        if (t + 1 < tEnd) {
            u0 = __ldg(&g_U[((t + 1) * BATCH + ob0) * DDIM + og0]);
            u1 = __ldg(&g_U[((t + 1) * BATCH + ob1) * DDIM + og1]);
        }

        asm volatile("barrier.cluster.wait.aligned;\n" ::: "memory");

        if (t >= tOut) {
            g_H[(t * BATCH + ob0) * DDIM + og0] = v0;
            g_H[(t * BATCH + ob1) * DDIM + og1] = v1;
        }
    }
}

// ---------------------------------------------------------------------------
extern "C" void kernel_launch(void* const* d_in, const int* in_sizes, int n_in,
                              void* d_out, int out_size)
{
    (void)in_sizes; (void)n_in; (void)out_size;
    const float* X  = (const float*)d_in[0];  // sequence [T,B,D]
    const float* h0 = (const float*)d_in[1];
    const float* WA = (const float*)d_in[2];
    const float* bA = (const float*)d_in[3];
    const float* WB = (const float*)d_in[4];
    const float* bB = (const float*)d_in[5];
    const float* WC = (const float*)d_in[6];
    const float* bC = (const float*)d_in[7];
    const float* WD = (const float*)d_in[8];
    const float* bD = (const float*)d_in[9];
    float* Y = (float*)d_out;

    float* U = nullptr; float* H = nullptr;
    cudaGetSymbolAddress((void**)&U, g_U);
    cudaGetSymbolAddress((void**)&H, g_H);

    cudaFuncSetAttribute(ssm_scan, cudaFuncAttributeMaxDynamicSharedMemorySize,
                         (64 * 128) * 16 + 4096 * 4 + 4096 * 4);   // 160 KB

    const dim3 tg(M_ROWS / 128, DDIM / 64);    // (128, 8)

    // 1) U = X @ WB^T + bA + bB   (bA folded: added every recurrence step)
    mma_gemm<0><<<tg, 256>>>(X, WB, bA, bB, nullptr, U);
    // 2) V = X @ WD^T + bC + bD   -> stored directly into Y (d_out)
    mma_gemm<0><<<tg, 256>>>(X, WD, bC, bD, nullptr, Y);
    // 3) Chunked scan -> g_H
    ssm_scan<<<NCHUNK * CL_SZ, 256, (64 * 128) * 16 + 4096 * 4 + 4096 * 4>>>(WA, h0);
    // 4) Y = H @ WC^T + V (in place: same-element read-then-write per thread)
    mma_gemm<1><<<tg, 256>>>(H, WC, nullptr, nullptr, Y, Y);
}